// round 14
// baseline (speedup 1.0000x reference)
#include <cuda_runtime.h>
#include <cstdint>

#define HDIM 128
#define NMAX 100032
#define EMAX 1600000
#define GMAX 1024
#define NCLS 10
#define BN_EPS 1e-5
#define SLOPE 0.01f
#define SCAN_CHUNK 2048
#define MAXBLK 64

// ---------------- device scratch (static, no allocation) ----------------
__device__ __align__(16) float  g_agg[(size_t)NMAX * HDIM];
__device__ __align__(16) float  g_h  [(size_t)NMAX * HDIM];
__device__ __align__(16) float  g_hg [GMAX * HDIM];
__device__ __align__(16) float  g_cnt[GMAX];
__device__ __align__(16) double g_stats[2 * HDIM];
__device__ __align__(16) float  g_coef [2 * HDIM];
__device__ int g_deg   [NMAX];
__device__ int g_rowptr[NMAX + 1];
__device__ int g_cur   [NMAX];
__device__ int g_eidx  [EMAX];
__device__ int g_bsum  [MAXBLK];
__device__ int g_boff  [MAXBLK];

__device__ __forceinline__ float lrelu(float x) { return x > 0.f ? x : SLOPE * x; }

// ---------------- zero small scratch + CSR counters ----------------
__global__ void zero_kernel(int N) {
    int idx    = blockIdx.x * blockDim.x + threadIdx.x;
    int stride = gridDim.x * blockDim.x;
    float4 z = make_float4(0.f, 0.f, 0.f, 0.f);
    float4* h4 = reinterpret_cast<float4*>(g_hg);
    for (int i = idx; i < (GMAX * HDIM) >> 2; i += stride) h4[i] = z;
    for (int i = idx; i < N; i += stride) g_deg[i] = 0;
    if (idx < GMAX) g_cnt[idx] = 0.f;
    if (idx < 2 * HDIM) g_stats[idx] = 0.0;
}

// ---------------- combined edge histogram + per-graph node counts ----------------
__global__ void hist_kernel(const int* __restrict__ dst,
                            const int* __restrict__ batch, int E, int N) {
    int e = blockIdx.x * blockDim.x + threadIdx.x;
    if (e < E) atomicAdd(&g_deg[dst[e]], 1);
    if (e < N) atomicAdd(&g_cnt[batch[e]], 1.0f);
}

// ---------------- CSR build: 3-phase multi-block exclusive scan ----------------
__global__ void scan1_kernel(int N) {
    __shared__ int ts[256];
    int b = blockIdx.x;
    int t = threadIdx.x;
    int base = b * SCAN_CHUNK + t * 8;
    int v[8];
    int s = 0;
#pragma unroll
    for (int i = 0; i < 8; i++) {
        int idx = base + i;
        v[i] = (idx < N) ? g_deg[idx] : 0;
        s += v[i];
    }
    ts[t] = s;
    __syncthreads();
#pragma unroll
    for (int off = 1; off < 256; off <<= 1) {
        int x = (t >= off) ? ts[t - off] : 0;
        __syncthreads();
        ts[t] += x;
        __syncthreads();
    }
    int run = ts[t] - s;
#pragma unroll
    for (int i = 0; i < 8; i++) {
        int idx = base + i;
        if (idx < N) g_rowptr[idx] = run;
        run += v[i];
    }
    if (t == 255) g_bsum[b] = ts[255];
}

__global__ void scan2_kernel(int nb) {
    __shared__ int ts[MAXBLK];
    int t = threadIdx.x;
    int v = (t < nb) ? g_bsum[t] : 0;
    ts[t] = v;
    __syncthreads();
#pragma unroll
    for (int off = 1; off < MAXBLK; off <<= 1) {
        int x = (t >= off) ? ts[t - off] : 0;
        __syncthreads();
        ts[t] += x;
        __syncthreads();
    }
    g_boff[t] = ts[t] - v;
}

// phase 3: add block offsets; also init fill cursor to absolute rowptr
__global__ void scan3_kernel(int N, int nb) {
    int i = blockIdx.x * blockDim.x + threadIdx.x;
    if (i < N) {
        int rp = g_rowptr[i] + g_boff[i / SCAN_CHUNK];
        g_rowptr[i] = rp;
        g_cur[i]    = rp;
    }
    if (i == N) g_rowptr[N] = g_boff[nb - 1] + g_bsum[nb - 1];
}

__global__ void fill_kernel(const int* __restrict__ src,
                            const int* __restrict__ dst, int E) {
    int e = blockIdx.x * blockDim.x + threadIdx.x;
    if (e < E) {
        int pos = atomicAdd(&g_cur[dst[e]], 1);   // absolute cursor
        g_eidx[pos] = src[e];
    }
}

// ---------------- gather aggregation: agg[i] = BN?( x[i] + sum_{j->i} x[j] ) ----------------
// warp per node; unroll-8 for deeper MLP in the random L2 gather
template<int APPLY_BN>
__global__ void aggregate_kernel(const float* __restrict__ Xext, int N) {
    int i = (blockIdx.x * blockDim.x + threadIdx.x) >> 5;
    if (i >= N) return;
    int lane = threadIdx.x & 31;
    const float* X = APPLY_BN ? g_h : Xext;
    int base = g_rowptr[i];
    int end  = g_rowptr[i + 1];

    float4 acc = *reinterpret_cast<const float4*>(X + (size_t)i * HDIM + lane * 4);
    int e = base;
    for (; e + 8 <= end; e += 8) {
        int s0 = g_eidx[e],     s1 = g_eidx[e + 1], s2 = g_eidx[e + 2], s3 = g_eidx[e + 3];
        int s4 = g_eidx[e + 4], s5 = g_eidx[e + 5], s6 = g_eidx[e + 6], s7 = g_eidx[e + 7];
        float4 v0 = *reinterpret_cast<const float4*>(X + (size_t)s0 * HDIM + lane * 4);
        float4 v1 = *reinterpret_cast<const float4*>(X + (size_t)s1 * HDIM + lane * 4);
        float4 v2 = *reinterpret_cast<const float4*>(X + (size_t)s2 * HDIM + lane * 4);
        float4 v3 = *reinterpret_cast<const float4*>(X + (size_t)s3 * HDIM + lane * 4);
        float4 v4 = *reinterpret_cast<const float4*>(X + (size_t)s4 * HDIM + lane * 4);
        float4 v5 = *reinterpret_cast<const float4*>(X + (size_t)s5 * HDIM + lane * 4);
        float4 v6 = *reinterpret_cast<const float4*>(X + (size_t)s6 * HDIM + lane * 4);
        float4 v7 = *reinterpret_cast<const float4*>(X + (size_t)s7 * HDIM + lane * 4);
        acc.x += (v0.x + v1.x) + (v2.x + v3.x) + (v4.x + v5.x) + (v6.x + v7.x);
        acc.y += (v0.y + v1.y) + (v2.y + v3.y) + (v4.y + v5.y) + (v6.y + v7.y);
        acc.z += (v0.z + v1.z) + (v2.z + v3.z) + (v4.z + v5.z) + (v6.z + v7.z);
        acc.w += (v0.w + v1.w) + (v2.w + v3.w) + (v4.w + v5.w) + (v6.w + v7.w);
    }
    for (; e + 4 <= end; e += 4) {
        int s0 = g_eidx[e], s1 = g_eidx[e + 1], s2 = g_eidx[e + 2], s3 = g_eidx[e + 3];
        float4 v0 = *reinterpret_cast<const float4*>(X + (size_t)s0 * HDIM + lane * 4);
        float4 v1 = *reinterpret_cast<const float4*>(X + (size_t)s1 * HDIM + lane * 4);
        float4 v2 = *reinterpret_cast<const float4*>(X + (size_t)s2 * HDIM + lane * 4);
        float4 v3 = *reinterpret_cast<const float4*>(X + (size_t)s3 * HDIM + lane * 4);
        acc.x += v0.x + v1.x + v2.x + v3.x;
        acc.y += v0.y + v1.y + v2.y + v3.y;
        acc.z += v0.z + v1.z + v2.z + v3.z;
        acc.w += v0.w + v1.w + v2.w + v3.w;
    }
    for (; e < end; e++) {
        int s = g_eidx[e];
        float4 v = *reinterpret_cast<const float4*>(X + (size_t)s * HDIM + lane * 4);
        acc.x += v.x; acc.y += v.y; acc.z += v.z; acc.w += v.w;
    }
    if (APPLY_BN) {
        float cnt = (float)(end - base + 1);
        float4 a = *reinterpret_cast<const float4*>(&g_coef[lane * 4]);
        float4 c = *reinterpret_cast<const float4*>(&g_coef[HDIM + lane * 4]);
        acc.x = fmaf(a.x, acc.x, cnt * c.x);
        acc.y = fmaf(a.y, acc.y, cnt * c.y);
        acc.z = fmaf(a.z, acc.z, cnt * c.z);
        acc.w = fmaf(a.w, acc.w, cnt * c.w);
    }
    *reinterpret_cast<float4*>(g_agg + (size_t)i * HDIM + lane * 4) = acc;
}

// ---------------- fused GIN layer: h = leaky(A@Wa+ba) @ Wb + bb (+leaky/stats/pool) ----------
// 256 threads, 64-row tile, per-thread 8x4. Phase 1: A=g_agg -> U (smem).
// Phase 2: U @ Wb. POOL=0: out g_h + BN stats. POOL=1: pooled raw graph sums + BN stats.
template<int POOL>
__global__ void __launch_bounds__(256)
gin_layer(const float* __restrict__ Wa, const float* __restrict__ ba,
          const float* __restrict__ Wb, const float* __restrict__ bb,
          const int* __restrict__ batch, int N) {
    __shared__ __align__(16) float As[16][72];
    __shared__ __align__(16) float Ws[16 * HDIM];
    __shared__ __align__(16) float U [64 * HDIM];
    __shared__ float csum[HDIM];
    __shared__ float csq [HDIM];

    const int tid  = threadIdx.x;
    const int tcol = tid & 31;
    const int trow = tid >> 5;
    const int row0 = blockIdx.x * 64;

    float acc[8][4];
#pragma unroll
    for (int i = 0; i < 8; i++)
#pragma unroll
        for (int j = 0; j < 4; j++) acc[i][j] = 0.f;

    const int lr = tid >> 2;
    const int lk = (tid & 3) * 4;
    const int grow = row0 + lr;
    const bool rowOK = grow < N;

    // ---------------- phase 1: U = leaky(A @ Wa + ba) ----------------
    float4 avP = make_float4(0.f, 0.f, 0.f, 0.f);
    float4 wvP0, wvP1;
    if (rowOK)
        avP = *reinterpret_cast<const float4*>(g_agg + (size_t)grow * HDIM + lk);
    {
        const float4* wsrc = reinterpret_cast<const float4*>(Wa);
        wvP0 = wsrc[tid];
        wvP1 = wsrc[tid + 256];
    }

    for (int ci = 0; ci < 8; ci++) {
        As[lk + 0][lr] = avP.x;
        As[lk + 1][lr] = avP.y;
        As[lk + 2][lr] = avP.z;
        As[lk + 3][lr] = avP.w;
        {
            float4* wdst = reinterpret_cast<float4*>(Ws);
            wdst[tid]       = wvP0;
            wdst[tid + 256] = wvP1;
        }
        __syncthreads();

        if (ci < 7) {
            int k0n = (ci + 1) * 16;
            if (rowOK)
                avP = *reinterpret_cast<const float4*>(g_agg + (size_t)grow * HDIM + k0n + lk);
            const float4* wsrc = reinterpret_cast<const float4*>(Wa + k0n * HDIM);
            wvP0 = wsrc[tid];
            wvP1 = wsrc[tid + 256];
        } else {
            // prefetch Wb chunk 0 for phase 2
            const float4* wsrc = reinterpret_cast<const float4*>(Wb);
            wvP0 = wsrc[tid];
            wvP1 = wsrc[tid + 256];
        }

#pragma unroll
        for (int kk = 0; kk < 16; kk++) {
            float4 w  = *reinterpret_cast<float4*>(&Ws[kk * HDIM + tcol * 4]);
            float4 a0 = *reinterpret_cast<float4*>(&As[kk][trow * 8]);
            float4 a1 = *reinterpret_cast<float4*>(&As[kk][trow * 8 + 4]);
            float a[8] = {a0.x, a0.y, a0.z, a0.w, a1.x, a1.y, a1.z, a1.w};
#pragma unroll
            for (int i = 0; i < 8; i++) {
                acc[i][0] = fmaf(a[i], w.x, acc[i][0]);
                acc[i][1] = fmaf(a[i], w.y, acc[i][1]);
                acc[i][2] = fmaf(a[i], w.z, acc[i][2]);
                acc[i][3] = fmaf(a[i], w.w, acc[i][3]);
            }
        }
        __syncthreads();
    }

    // phase-1 epilogue: U[row][col] = leaky(acc + ba); per-warp rows -> contiguous stores
    {
        float4 bv = *reinterpret_cast<const float4*>(ba + tcol * 4);
#pragma unroll
        for (int i = 0; i < 8; i++) {
            float4 o;
            o.x = lrelu(acc[i][0] + bv.x);
            o.y = lrelu(acc[i][1] + bv.y);
            o.z = lrelu(acc[i][2] + bv.z);
            o.w = lrelu(acc[i][3] + bv.w);
            *reinterpret_cast<float4*>(&U[(trow * 8 + i) * HDIM + tcol * 4]) = o;
        }
    }
#pragma unroll
    for (int i = 0; i < 8; i++)
#pragma unroll
        for (int j = 0; j < 4; j++) acc[i][j] = 0.f;
    __syncthreads();

    // ---------------- phase 2: out = U @ Wb ----------------
    for (int ci = 0; ci < 8; ci++) {
        {
            float4* wdst = reinterpret_cast<float4*>(Ws);
            wdst[tid]       = wvP0;
            wdst[tid + 256] = wvP1;
        }
        __syncthreads();

        if (ci < 7) {
            int k0n = (ci + 1) * 16;
            const float4* wsrc = reinterpret_cast<const float4*>(Wb + k0n * HDIM);
            wvP0 = wsrc[tid];
            wvP1 = wsrc[tid + 256];
        }

        const int k0 = ci * 16;
#pragma unroll
        for (int kq = 0; kq < 4; kq++) {
            float4 w0 = *reinterpret_cast<float4*>(&Ws[(kq * 4 + 0) * HDIM + tcol * 4]);
            float4 w1 = *reinterpret_cast<float4*>(&Ws[(kq * 4 + 1) * HDIM + tcol * 4]);
            float4 w2 = *reinterpret_cast<float4*>(&Ws[(kq * 4 + 2) * HDIM + tcol * 4]);
            float4 w3 = *reinterpret_cast<float4*>(&Ws[(kq * 4 + 3) * HDIM + tcol * 4]);
#pragma unroll
            for (int i = 0; i < 8; i++) {
                float4 a = *reinterpret_cast<float4*>(&U[(trow * 8 + i) * HDIM + k0 + kq * 4]);
                acc[i][0] = fmaf(a.x, w0.x, acc[i][0]);
                acc[i][1] = fmaf(a.x, w0.y, acc[i][1]);
                acc[i][2] = fmaf(a.x, w0.z, acc[i][2]);
                acc[i][3] = fmaf(a.x, w0.w, acc[i][3]);
                acc[i][0] = fmaf(a.y, w1.x, acc[i][0]);
                acc[i][1] = fmaf(a.y, w1.y, acc[i][1]);
                acc[i][2] = fmaf(a.y, w1.z, acc[i][2]);
                acc[i][3] = fmaf(a.y, w1.w, acc[i][3]);
                acc[i][0] = fmaf(a.z, w2.x, acc[i][0]);
                acc[i][1] = fmaf(a.z, w2.y, acc[i][1]);
                acc[i][2] = fmaf(a.z, w2.z, acc[i][2]);
                acc[i][3] = fmaf(a.z, w2.w, acc[i][3]);
                acc[i][0] = fmaf(a.w, w3.x, acc[i][0]);
                acc[i][1] = fmaf(a.w, w3.y, acc[i][1]);
                acc[i][2] = fmaf(a.w, w3.z, acc[i][2]);
                acc[i][3] = fmaf(a.w, w3.w, acc[i][3]);
            }
        }
        __syncthreads();
    }

    // ---------------- phase-2 epilogue ----------------
    float4 bv = *reinterpret_cast<const float4*>(bb + tcol * 4);
    float s0[4] = {0.f, 0.f, 0.f, 0.f};
    float s1[4] = {0.f, 0.f, 0.f, 0.f};
    int curg = -1;
    float p[4] = {0.f, 0.f, 0.f, 0.f};

#pragma unroll
    for (int i = 0; i < 8; i++) {
        int r = row0 + trow * 8 + i;
        if (r < N) {
            float4 o;
            o.x = lrelu(acc[i][0] + bv.x);
            o.y = lrelu(acc[i][1] + bv.y);
            o.z = lrelu(acc[i][2] + bv.z);
            o.w = lrelu(acc[i][3] + bv.w);
            s0[0] += o.x; s1[0] += o.x * o.x;
            s0[1] += o.y; s1[1] += o.y * o.y;
            s0[2] += o.z; s1[2] += o.z * o.z;
            s0[3] += o.w; s1[3] += o.w * o.w;
            if (!POOL) {
                *reinterpret_cast<float4*>(g_h + (size_t)r * HDIM + tcol * 4) = o;
            } else {
                int g = batch[r];
                if (g != curg) {
                    if (curg >= 0) {
                        float* dp = g_hg + (size_t)curg * HDIM + tcol * 4;
                        asm volatile("red.global.add.v4.f32 [%0], {%1, %2, %3, %4};"
                                     :: "l"(dp), "f"(p[0]), "f"(p[1]), "f"(p[2]), "f"(p[3]) : "memory");
                    }
                    curg = g;
                    p[0] = o.x; p[1] = o.y; p[2] = o.z; p[3] = o.w;
                } else {
                    p[0] += o.x; p[1] += o.y; p[2] += o.z; p[3] += o.w;
                }
            }
        }
    }
    if (POOL && curg >= 0) {
        float* dp = g_hg + (size_t)curg * HDIM + tcol * 4;
        asm volatile("red.global.add.v4.f32 [%0], {%1, %2, %3, %4};"
                     :: "l"(dp), "f"(p[0]), "f"(p[1]), "f"(p[2]), "f"(p[3]) : "memory");
    }

    if (tid < HDIM) { csum[tid] = 0.f; csq[tid] = 0.f; }
    __syncthreads();
#pragma unroll
    for (int j = 0; j < 4; j++) {
        atomicAdd(&csum[tcol * 4 + j], s0[j]);
        atomicAdd(&csq [tcol * 4 + j], s1[j]);
    }
    __syncthreads();
    if (tid < HDIM) {
        atomicAdd(&g_stats[tid],        (double)csum[tid]);
        atomicAdd(&g_stats[HDIM + tid], (double)csq[tid]);
    }
}

// ---------------- BN coefficients (self-zeroes stats for next layer) ----------------
__global__ void coef_kernel(const float* __restrict__ gamma,
                            const float* __restrict__ beta, int N) {
    int c = threadIdx.x;
    double mean = g_stats[c] / (double)N;
    double var  = g_stats[HDIM + c] / (double)N - mean * mean;
    float a = (float)((double)gamma[c] / sqrt(var + (double)BN_EPS));
    g_coef[c]        = a;
    g_coef[HDIM + c] = beta[c] - a * (float)mean;
    g_stats[c] = 0.0;
    g_stats[HDIM + c] = 0.0;
}

// ---------------- head: hg = a2*raw + c2*cnt, MLP + log_softmax ----------------
__global__ void head_kernel(const float* __restrict__ fcW1, const float* __restrict__ fcb1,
                            const float* __restrict__ fcW2, const float* __restrict__ fcb2,
                            float* __restrict__ out) {
    __shared__ float s[HDIM];
    __shared__ float y[HDIM];
    __shared__ float z[NCLS];
    __shared__ float red2[2];
    int g = blockIdx.x;
    int j = threadIdx.x;

    float cnt = g_cnt[g];
    s[j] = g_coef[j] * g_hg[g * HDIM + j] + g_coef[HDIM + j] * cnt;
    __syncthreads();

    float acc = fcb1[j];
#pragma unroll 8
    for (int k = 0; k < HDIM; k++) acc += s[k] * fcW1[k * HDIM + j];
    y[j] = lrelu(acc);
    __syncthreads();

    if (j < NCLS) {
        float acc2 = fcb2[j];
#pragma unroll 8
        for (int k = 0; k < HDIM; k++) acc2 += y[k] * fcW2[k * NCLS + j];
        z[j] = acc2;
    }
    __syncthreads();

    if (j == 0) {
        float m = z[0];
#pragma unroll
        for (int c = 1; c < NCLS; c++) m = fmaxf(m, z[c]);
        float se = 0.f;
#pragma unroll
        for (int c = 0; c < NCLS; c++) se += expf(z[c] - m);
        red2[0] = m;
        red2[1] = logf(se);
    }
    __syncthreads();
    if (j < NCLS) out[g * NCLS + j] = z[j] - red2[0] - red2[1];
}

// ---------------- launch ----------------
extern "C" void kernel_launch(void* const* d_in, const int* in_sizes, int n_in,
                              void* d_out, int out_size) {
    const float* x    = (const float*)d_in[0];
    const float* W1a  = (const float*)d_in[1];
    const float* b1a  = (const float*)d_in[2];
    const float* W1b  = (const float*)d_in[3];
    const float* b1b  = (const float*)d_in[4];
    const float* g1   = (const float*)d_in[5];
    const float* be1  = (const float*)d_in[6];
    const float* W2a  = (const float*)d_in[7];
    const float* b2a  = (const float*)d_in[8];
    const float* W2b  = (const float*)d_in[9];
    const float* b2b  = (const float*)d_in[10];
    const float* g2   = (const float*)d_in[11];
    const float* be2  = (const float*)d_in[12];
    const float* fcW1 = (const float*)d_in[13];
    const float* fcb1 = (const float*)d_in[14];
    const float* fcW2 = (const float*)d_in[15];
    const float* fcb2 = (const float*)d_in[16];
    const int* ei     = (const int*)d_in[17];   // int32 (JAX x64 disabled)
    const int* batch  = (const int*)d_in[18];   // int32
    float* out = (float*)d_out;

    const int N = in_sizes[0] / HDIM;
    const int E = in_sizes[17] / 2;
    const int* esrc = ei;
    const int* edst = ei + E;

    const int gemmBlocks = (N + 63) / 64;
    const int aggBlocks  = (N + 7) / 8;
    const int eBlocks    = (E + 255) / 256;
    const int scanBlocks = (N + SCAN_CHUNK - 1) / SCAN_CHUNK;

    // ---- CSR build (once, reused by both layers) ----
    zero_kernel<<<512, 256>>>(N);
    hist_kernel<<<eBlocks, 256>>>(edst, batch, E, N);
    scan1_kernel<<<scanBlocks, 256>>>(N);
    scan2_kernel<<<1, MAXBLK>>>(scanBlocks);
    scan3_kernel<<<(N + 256) / 256, 256>>>(N, scanBlocks);
    fill_kernel<<<eBlocks, 256>>>(esrc, edst, E);

    // ---- layer 1 (fused double GEMM) ----
    aggregate_kernel<0><<<aggBlocks, 256>>>(x, N);
    gin_layer<0><<<gemmBlocks, 256>>>(W1a, b1a, W1b, b1b, nullptr, N);
    coef_kernel<<<1, HDIM>>>(g1, be1, N);

    // ---- layer 2 (BN1 folded into aggregation; pool fused into epilogue) ----
    aggregate_kernel<1><<<aggBlocks, 256>>>(nullptr, N);
    gin_layer<1><<<gemmBlocks, 256>>>(W2a, b2a, W2b, b2b, batch, N);
    coef_kernel<<<1, HDIM>>>(g2, be2, N);

    // ---- head ----
    head_kernel<<<GMAX, HDIM>>>(fcW1, fcb1, fcW2, fcb2, out);
}

// round 15
// speedup vs baseline: 1.4880x; 1.4880x over previous
#include <cuda_runtime.h>
#include <cstdint>

#define HDIM 128
#define NMAX 100032
#define EMAX 1600000
#define GMAX 1024
#define NCLS 10
#define BN_EPS 1e-5
#define SLOPE 0.01f
#define SCAN_CHUNK 2048
#define MAXBLK 64

// ---------------- device scratch (static, no allocation) ----------------
__device__ __align__(16) float  g_agg[(size_t)NMAX * HDIM];
__device__ __align__(16) float  g_h  [(size_t)NMAX * HDIM];
__device__ __align__(16) float  g_hg [GMAX * HDIM];
__device__ __align__(16) float  g_cnt[GMAX];
__device__ __align__(16) double g_stats[2 * HDIM];
__device__ __align__(16) float  g_coef [2 * HDIM];
__device__ int g_deg   [NMAX];
__device__ int g_rowptr[NMAX + 1];
__device__ int g_cur   [NMAX];
__device__ int g_eidx  [EMAX];
__device__ int g_bsum  [MAXBLK];

__device__ __forceinline__ float lrelu(float x) { return x > 0.f ? x : SLOPE * x; }

// ---------------- zero small scratch + CSR counters ----------------
__global__ void zero_kernel(int N) {
    int idx    = blockIdx.x * blockDim.x + threadIdx.x;
    int stride = gridDim.x * blockDim.x;
    float4 z = make_float4(0.f, 0.f, 0.f, 0.f);
    float4* h4 = reinterpret_cast<float4*>(g_hg);
    for (int i = idx; i < (GMAX * HDIM) >> 2; i += stride) h4[i] = z;
    for (int i = idx; i < N; i += stride) g_deg[i] = 0;
    if (idx < GMAX) g_cnt[idx] = 0.f;
    if (idx < 2 * HDIM) g_stats[idx] = 0.0;
}

// ---------------- combined edge histogram + per-graph node counts ----------------
__global__ void hist_kernel(const int* __restrict__ dst,
                            const int* __restrict__ batch, int E, int N) {
    int e = blockIdx.x * blockDim.x + threadIdx.x;
    if (e < E) atomicAdd(&g_deg[dst[e]], 1);
    if (e < N) atomicAdd(&g_cnt[batch[e]], 1.0f);
}

// ---------------- CSR build: 2-phase multi-block exclusive scan ----------------
// phase 1: per-block exclusive scan over 2048-element chunks + block totals
__global__ void scan1_kernel(int N) {
    __shared__ int ts[256];
    int b = blockIdx.x;
    int t = threadIdx.x;
    int base = b * SCAN_CHUNK + t * 8;
    int v[8];
    int s = 0;
#pragma unroll
    for (int i = 0; i < 8; i++) {
        int idx = base + i;
        v[i] = (idx < N) ? g_deg[idx] : 0;
        s += v[i];
    }
    ts[t] = s;
    __syncthreads();
#pragma unroll
    for (int off = 1; off < 256; off <<= 1) {
        int x = (t >= off) ? ts[t - off] : 0;
        __syncthreads();
        ts[t] += x;
        __syncthreads();
    }
    int run = ts[t] - s;
#pragma unroll
    for (int i = 0; i < 8; i++) {
        int idx = base + i;
        if (idx < N) g_rowptr[idx] = run;
        run += v[i];
    }
    if (t == 255) g_bsum[b] = ts[255];
}

// phase 2 (scan2 folded in): every block recomputes the 64-entry block-total
// prefix in smem, then adds the per-chunk offset; inits fill cursor too.
__global__ void scan3_kernel(int N, int nb) {
    __shared__ int ts[MAXBLK];
    int t = threadIdx.x;
    if (t < MAXBLK) ts[t] = (t < nb) ? g_bsum[t] : 0;
    __syncthreads();
    // Hillis-Steele inclusive scan on 64 entries (warps 0-1 only do work)
#pragma unroll
    for (int off = 1; off < MAXBLK; off <<= 1) {
        int x = (t >= off && t < MAXBLK) ? ts[t - off] : 0;
        __syncthreads();
        if (t < MAXBLK) ts[t] += x;
        __syncthreads();
    }
    int i = blockIdx.x * blockDim.x + t;
    if (i < N) {
        int chunk = i / SCAN_CHUNK;
        int off = (chunk > 0) ? ts[chunk - 1] : 0;   // exclusive block offset
        int rp = g_rowptr[i] + off;
        g_rowptr[i] = rp;
        g_cur[i]    = rp;
    }
    if (i == N) g_rowptr[N] = ts[nb - 1];
}

__global__ void fill_kernel(const int* __restrict__ src,
                            const int* __restrict__ dst, int E) {
    int e = blockIdx.x * blockDim.x + threadIdx.x;
    if (e < E) {
        int pos = atomicAdd(&g_cur[dst[e]], 1);   // absolute cursor
        g_eidx[pos] = src[e];
    }
}

// ---------------- gather aggregation: agg[i] = BN?( x[i] + sum_{j->i} x[j] ) ----------------
// warp per node; unroll-4 (MLP sweet spot — unroll-8 overflows the L1tex queue)
template<int APPLY_BN>
__global__ void aggregate_kernel(const float* __restrict__ Xext, int N) {
    int i = (blockIdx.x * blockDim.x + threadIdx.x) >> 5;
    if (i >= N) return;
    int lane = threadIdx.x & 31;
    const float* X = APPLY_BN ? g_h : Xext;
    int base = g_rowptr[i];
    int end  = g_rowptr[i + 1];

    float4 acc = *reinterpret_cast<const float4*>(X + (size_t)i * HDIM + lane * 4);
    int e = base;
    for (; e + 4 <= end; e += 4) {
        int s0 = g_eidx[e], s1 = g_eidx[e + 1], s2 = g_eidx[e + 2], s3 = g_eidx[e + 3];
        float4 v0 = *reinterpret_cast<const float4*>(X + (size_t)s0 * HDIM + lane * 4);
        float4 v1 = *reinterpret_cast<const float4*>(X + (size_t)s1 * HDIM + lane * 4);
        float4 v2 = *reinterpret_cast<const float4*>(X + (size_t)s2 * HDIM + lane * 4);
        float4 v3 = *reinterpret_cast<const float4*>(X + (size_t)s3 * HDIM + lane * 4);
        acc.x += v0.x + v1.x + v2.x + v3.x;
        acc.y += v0.y + v1.y + v2.y + v3.y;
        acc.z += v0.z + v1.z + v2.z + v3.z;
        acc.w += v0.w + v1.w + v2.w + v3.w;
    }
    for (; e < end; e++) {
        int s = g_eidx[e];
        float4 v = *reinterpret_cast<const float4*>(X + (size_t)s * HDIM + lane * 4);
        acc.x += v.x; acc.y += v.y; acc.z += v.z; acc.w += v.w;
    }
    if (APPLY_BN) {
        float cnt = (float)(end - base + 1);
        float4 a = *reinterpret_cast<const float4*>(&g_coef[lane * 4]);
        float4 c = *reinterpret_cast<const float4*>(&g_coef[HDIM + lane * 4]);
        acc.x = fmaf(a.x, acc.x, cnt * c.x);
        acc.y = fmaf(a.y, acc.y, cnt * c.y);
        acc.z = fmaf(a.z, acc.z, cnt * c.z);
        acc.w = fmaf(a.w, acc.w, cnt * c.w);
    }
    *reinterpret_cast<float4*>(g_agg + (size_t)i * HDIM + lane * 4) = acc;
}

// ---------------- fused GIN layer: h = leaky(A@Wa+ba) @ Wb + bb (+leaky/stats/pool) ----------
// 256 threads, 64-row tile, per-thread 8x4. Phase 1: A=g_agg -> U (smem).
// Phase 2: U @ Wb. POOL=0: out g_h + BN stats. POOL=1: pooled raw graph sums + BN stats.
template<int POOL>
__global__ void __launch_bounds__(256)
gin_layer(const float* __restrict__ Wa, const float* __restrict__ ba,
          const float* __restrict__ Wb, const float* __restrict__ bb,
          const int* __restrict__ batch, int N) {
    __shared__ __align__(16) float As[16][72];
    __shared__ __align__(16) float Ws[16 * HDIM];
    __shared__ __align__(16) float U [64 * HDIM];
    __shared__ float csum[HDIM];
    __shared__ float csq [HDIM];

    const int tid  = threadIdx.x;
    const int tcol = tid & 31;
    const int trow = tid >> 5;
    const int row0 = blockIdx.x * 64;

    float acc[8][4];
#pragma unroll
    for (int i = 0; i < 8; i++)
#pragma unroll
        for (int j = 0; j < 4; j++) acc[i][j] = 0.f;

    const int lr = tid >> 2;
    const int lk = (tid & 3) * 4;
    const int grow = row0 + lr;
    const bool rowOK = grow < N;

    // ---------------- phase 1: U = leaky(A @ Wa + ba) ----------------
    float4 avP = make_float4(0.f, 0.f, 0.f, 0.f);
    float4 wvP0, wvP1;
    if (rowOK)
        avP = *reinterpret_cast<const float4*>(g_agg + (size_t)grow * HDIM + lk);
    {
        const float4* wsrc = reinterpret_cast<const float4*>(Wa);
        wvP0 = wsrc[tid];
        wvP1 = wsrc[tid + 256];
    }

    for (int ci = 0; ci < 8; ci++) {
        As[lk + 0][lr] = avP.x;
        As[lk + 1][lr] = avP.y;
        As[lk + 2][lr] = avP.z;
        As[lk + 3][lr] = avP.w;
        {
            float4* wdst = reinterpret_cast<float4*>(Ws);
            wdst[tid]       = wvP0;
            wdst[tid + 256] = wvP1;
        }
        __syncthreads();

        if (ci < 7) {
            int k0n = (ci + 1) * 16;
            if (rowOK)
                avP = *reinterpret_cast<const float4*>(g_agg + (size_t)grow * HDIM + k0n + lk);
            const float4* wsrc = reinterpret_cast<const float4*>(Wa + k0n * HDIM);
            wvP0 = wsrc[tid];
            wvP1 = wsrc[tid + 256];
        } else {
            // prefetch Wb chunk 0 for phase 2
            const float4* wsrc = reinterpret_cast<const float4*>(Wb);
            wvP0 = wsrc[tid];
            wvP1 = wsrc[tid + 256];
        }

#pragma unroll
        for (int kk = 0; kk < 16; kk++) {
            float4 w  = *reinterpret_cast<float4*>(&Ws[kk * HDIM + tcol * 4]);
            float4 a0 = *reinterpret_cast<float4*>(&As[kk][trow * 8]);
            float4 a1 = *reinterpret_cast<float4*>(&As[kk][trow * 8 + 4]);
            float a[8] = {a0.x, a0.y, a0.z, a0.w, a1.x, a1.y, a1.z, a1.w};
#pragma unroll
            for (int i = 0; i < 8; i++) {
                acc[i][0] = fmaf(a[i], w.x, acc[i][0]);
                acc[i][1] = fmaf(a[i], w.y, acc[i][1]);
                acc[i][2] = fmaf(a[i], w.z, acc[i][2]);
                acc[i][3] = fmaf(a[i], w.w, acc[i][3]);
            }
        }
        __syncthreads();
    }

    // phase-1 epilogue: U[row][col] = leaky(acc + ba); per-warp rows -> contiguous stores
    {
        float4 bv = *reinterpret_cast<const float4*>(ba + tcol * 4);
#pragma unroll
        for (int i = 0; i < 8; i++) {
            float4 o;
            o.x = lrelu(acc[i][0] + bv.x);
            o.y = lrelu(acc[i][1] + bv.y);
            o.z = lrelu(acc[i][2] + bv.z);
            o.w = lrelu(acc[i][3] + bv.w);
            *reinterpret_cast<float4*>(&U[(trow * 8 + i) * HDIM + tcol * 4]) = o;
        }
    }
#pragma unroll
    for (int i = 0; i < 8; i++)
#pragma unroll
        for (int j = 0; j < 4; j++) acc[i][j] = 0.f;
    __syncthreads();

    // ---------------- phase 2: out = U @ Wb ----------------
    for (int ci = 0; ci < 8; ci++) {
        {
            float4* wdst = reinterpret_cast<float4*>(Ws);
            wdst[tid]       = wvP0;
            wdst[tid + 256] = wvP1;
        }
        __syncthreads();

        if (ci < 7) {
            int k0n = (ci + 1) * 16;
            const float4* wsrc = reinterpret_cast<const float4*>(Wb + k0n * HDIM);
            wvP0 = wsrc[tid];
            wvP1 = wsrc[tid + 256];
        }

        const int k0 = ci * 16;
#pragma unroll
        for (int kq = 0; kq < 4; kq++) {
            float4 w0 = *reinterpret_cast<float4*>(&Ws[(kq * 4 + 0) * HDIM + tcol * 4]);
            float4 w1 = *reinterpret_cast<float4*>(&Ws[(kq * 4 + 1) * HDIM + tcol * 4]);
            float4 w2 = *reinterpret_cast<float4*>(&Ws[(kq * 4 + 2) * HDIM + tcol * 4]);
            float4 w3 = *reinterpret_cast<float4*>(&Ws[(kq * 4 + 3) * HDIM + tcol * 4]);
#pragma unroll
            for (int i = 0; i < 8; i++) {
                float4 a = *reinterpret_cast<float4*>(&U[(trow * 8 + i) * HDIM + k0 + kq * 4]);
                acc[i][0] = fmaf(a.x, w0.x, acc[i][0]);
                acc[i][1] = fmaf(a.x, w0.y, acc[i][1]);
                acc[i][2] = fmaf(a.x, w0.z, acc[i][2]);
                acc[i][3] = fmaf(a.x, w0.w, acc[i][3]);
                acc[i][0] = fmaf(a.y, w1.x, acc[i][0]);
                acc[i][1] = fmaf(a.y, w1.y, acc[i][1]);
                acc[i][2] = fmaf(a.y, w1.z, acc[i][2]);
                acc[i][3] = fmaf(a.y, w1.w, acc[i][3]);
                acc[i][0] = fmaf(a.z, w2.x, acc[i][0]);
                acc[i][1] = fmaf(a.z, w2.y, acc[i][1]);
                acc[i][2] = fmaf(a.z, w2.z, acc[i][2]);
                acc[i][3] = fmaf(a.z, w2.w, acc[i][3]);
                acc[i][0] = fmaf(a.w, w3.x, acc[i][0]);
                acc[i][1] = fmaf(a.w, w3.y, acc[i][1]);
                acc[i][2] = fmaf(a.w, w3.z, acc[i][2]);
                acc[i][3] = fmaf(a.w, w3.w, acc[i][3]);
            }
        }
        __syncthreads();
    }

    // ---------------- phase-2 epilogue ----------------
    float4 bv = *reinterpret_cast<const float4*>(bb + tcol * 4);
    float s0[4] = {0.f, 0.f, 0.f, 0.f};
    float s1[4] = {0.f, 0.f, 0.f, 0.f};
    int curg = -1;
    float p[4] = {0.f, 0.f, 0.f, 0.f};

#pragma unroll
    for (int i = 0; i < 8; i++) {
        int r = row0 + trow * 8 + i;
        if (r < N) {
            float4 o;
            o.x = lrelu(acc[i][0] + bv.x);
            o.y = lrelu(acc[i][1] + bv.y);
            o.z = lrelu(acc[i][2] + bv.z);
            o.w = lrelu(acc[i][3] + bv.w);
            s0[0] += o.x; s1[0] += o.x * o.x;
            s0[1] += o.y; s1[1] += o.y * o.y;
            s0[2] += o.z; s1[2] += o.z * o.z;
            s0[3] += o.w; s1[3] += o.w * o.w;
            if (!POOL) {
                *reinterpret_cast<float4*>(g_h + (size_t)r * HDIM + tcol * 4) = o;
            } else {
                int g = batch[r];
                if (g != curg) {
                    if (curg >= 0) {
                        float* dp = g_hg + (size_t)curg * HDIM + tcol * 4;
                        asm volatile("red.global.add.v4.f32 [%0], {%1, %2, %3, %4};"
                                     :: "l"(dp), "f"(p[0]), "f"(p[1]), "f"(p[2]), "f"(p[3]) : "memory");
                    }
                    curg = g;
                    p[0] = o.x; p[1] = o.y; p[2] = o.z; p[3] = o.w;
                } else {
                    p[0] += o.x; p[1] += o.y; p[2] += o.z; p[3] += o.w;
                }
            }
        }
    }
    if (POOL && curg >= 0) {
        float* dp = g_hg + (size_t)curg * HDIM + tcol * 4;
        asm volatile("red.global.add.v4.f32 [%0], {%1, %2, %3, %4};"
                     :: "l"(dp), "f"(p[0]), "f"(p[1]), "f"(p[2]), "f"(p[3]) : "memory");
    }

    if (tid < HDIM) { csum[tid] = 0.f; csq[tid] = 0.f; }
    __syncthreads();
#pragma unroll
    for (int j = 0; j < 4; j++) {
        atomicAdd(&csum[tcol * 4 + j], s0[j]);
        atomicAdd(&csq [tcol * 4 + j], s1[j]);
    }
    __syncthreads();
    if (tid < HDIM) {
        atomicAdd(&g_stats[tid],        (double)csum[tid]);
        atomicAdd(&g_stats[HDIM + tid], (double)csq[tid]);
    }
}

// ---------------- BN coefficients (self-zeroes stats for next layer) ----------------
__global__ void coef_kernel(const float* __restrict__ gamma,
                            const float* __restrict__ beta, int N) {
    int c = threadIdx.x;
    double mean = g_stats[c] / (double)N;
    double var  = g_stats[HDIM + c] / (double)N - mean * mean;
    float a = (float)((double)gamma[c] / sqrt(var + (double)BN_EPS));
    g_coef[c]        = a;
    g_coef[HDIM + c] = beta[c] - a * (float)mean;
    g_stats[c] = 0.0;
    g_stats[HDIM + c] = 0.0;
}

// ---------------- head: hg = a2*raw + c2*cnt, MLP + log_softmax ----------------
__global__ void head_kernel(const float* __restrict__ fcW1, const float* __restrict__ fcb1,
                            const float* __restrict__ fcW2, const float* __restrict__ fcb2,
                            float* __restrict__ out) {
    __shared__ float s[HDIM];
    __shared__ float y[HDIM];
    __shared__ float z[NCLS];
    __shared__ float red2[2];
    int g = blockIdx.x;
    int j = threadIdx.x;

    float cnt = g_cnt[g];
    s[j] = g_coef[j] * g_hg[g * HDIM + j] + g_coef[HDIM + j] * cnt;
    __syncthreads();

    float acc = fcb1[j];
#pragma unroll 8
    for (int k = 0; k < HDIM; k++) acc += s[k] * fcW1[k * HDIM + j];
    y[j] = lrelu(acc);
    __syncthreads();

    if (j < NCLS) {
        float acc2 = fcb2[j];
#pragma unroll 8
        for (int k = 0; k < HDIM; k++) acc2 += y[k] * fcW2[k * NCLS + j];
        z[j] = acc2;
    }
    __syncthreads();

    if (j == 0) {
        float m = z[0];
#pragma unroll
        for (int c = 1; c < NCLS; c++) m = fmaxf(m, z[c]);
        float se = 0.f;
#pragma unroll
        for (int c = 0; c < NCLS; c++) se += expf(z[c] - m);
        red2[0] = m;
        red2[1] = logf(se);
    }
    __syncthreads();
    if (j < NCLS) out[g * NCLS + j] = z[j] - red2[0] - red2[1];
}

// ---------------- launch ----------------
extern "C" void kernel_launch(void* const* d_in, const int* in_sizes, int n_in,
                              void* d_out, int out_size) {
    const float* x    = (const float*)d_in[0];
    const float* W1a  = (const float*)d_in[1];
    const float* b1a  = (const float*)d_in[2];
    const float* W1b  = (const float*)d_in[3];
    const float* b1b  = (const float*)d_in[4];
    const float* g1   = (const float*)d_in[5];
    const float* be1  = (const float*)d_in[6];
    const float* W2a  = (const float*)d_in[7];
    const float* b2a  = (const float*)d_in[8];
    const float* W2b  = (const float*)d_in[9];
    const float* b2b  = (const float*)d_in[10];
    const float* g2   = (const float*)d_in[11];
    const float* be2  = (const float*)d_in[12];
    const float* fcW1 = (const float*)d_in[13];
    const float* fcb1 = (const float*)d_in[14];
    const float* fcW2 = (const float*)d_in[15];
    const float* fcb2 = (const float*)d_in[16];
    const int* ei     = (const int*)d_in[17];   // int32 (JAX x64 disabled)
    const int* batch  = (const int*)d_in[18];   // int32
    float* out = (float*)d_out;

    const int N = in_sizes[0] / HDIM;
    const int E = in_sizes[17] / 2;
    const int* esrc = ei;
    const int* edst = ei + E;

    const int gemmBlocks = (N + 63) / 64;
    const int aggBlocks  = (N + 7) / 8;
    const int eBlocks    = (E + 255) / 256;
    const int scanBlocks = (N + SCAN_CHUNK - 1) / SCAN_CHUNK;

    // ---- CSR build (once, reused by both layers) ----
    zero_kernel<<<512, 256>>>(N);
    hist_kernel<<<eBlocks, 256>>>(edst, batch, E, N);
    scan1_kernel<<<scanBlocks, 256>>>(N);
    scan3_kernel<<<(N + 256) / 256, 256>>>(N, scanBlocks);
    fill_kernel<<<eBlocks, 256>>>(esrc, edst, E);

    // ---- layer 1 (fused double GEMM) ----
    aggregate_kernel<0><<<aggBlocks, 256>>>(x, N);
    gin_layer<0><<<gemmBlocks, 256>>>(W1a, b1a, W1b, b1b, nullptr, N);
    coef_kernel<<<1, HDIM>>>(g1, be1, N);

    // ---- layer 2 (BN1 folded into aggregation; pool fused into epilogue) ----
    aggregate_kernel<1><<<aggBlocks, 256>>>(nullptr, N);
    gin_layer<1><<<gemmBlocks, 256>>>(W2a, b2a, W2b, b2b, batch, N);
    coef_kernel<<<1, HDIM>>>(g2, be2, N);

    // ---- head ----
    head_kernel<<<GMAX, HDIM>>>(fcW1, fcb1, fcW2, fcb2, out);
}